// round 6
// baseline (speedup 1.0000x reference)
#include <cuda_runtime.h>
#include <cuda_bf16.h>
#include <cstdint>
#include <math.h>

#define NB 512
#define SEQ 128
#define D 256
#define NREST 65024            // NB*(SEQ-1)

#define BM 128
#define BN 256
#define BK 64
#define NKT (D / BK)           // 4
#define SSTRIDE 72             // bf16 elems; 144B row stride
#define A_STAGE (BM * SSTRIDE * 2)   // 18432
#define B_STAGE (BN * SSTRIDE * 2)   // 36864
#define GRIDX 4                // NB/BM
#define GRIDY (NREST / BN)     // 254
#define TOTAL_BLOCKS (GRIDX * GRIDY)

// dynamic smem layout (bytes)
#define SM_A 0
#define SM_B (3 * A_STAGE)                    // 55296
#define SM_MISC (SM_B + 3 * B_STAGE)          // 165888
#define SM_TOTAL (SM_MISC + BM*4 + BM*4 + BM*4 + BN*4 + 64)

// ---------------- device scratch ----------------
__device__ __nv_bfloat16 g_anchors[NB * D];
__device__ __nv_bfloat16 g_rest[(size_t)NREST * D];
__device__ int   g_labels[NB];
__device__ int   g_collab[NREST];
__device__ float g_tot[NB];
__device__ float g_pos[NB];
__device__ unsigned g_done;

__device__ __forceinline__ uint32_t smem_u32(const void* p) {
    return (uint32_t)__cvta_generic_to_shared(p);
}
__device__ __forceinline__ void cp_async16(uint32_t dst, const void* src) {
    asm volatile("cp.async.cg.shared.global [%0], [%1], 16;" :: "r"(dst), "l"(src) : "memory");
}
__device__ __forceinline__ void cp_commit() {
    asm volatile("cp.async.commit_group;" ::: "memory");
}
template <int N>
__device__ __forceinline__ void cp_wait() {
    asm volatile("cp.async.wait_group %0;" :: "n"(N) : "memory");
}

// ---------------- kernel 1: normalize + init ----------------
__global__ void normalize_kernel(const float* __restrict__ inp, const int* __restrict__ lab) {
    int gtid = blockIdx.x * 256 + threadIdx.x;
    if (gtid < NREST) g_collab[gtid] = lab[gtid / (SEQ - 1)];
    if (gtid < NB) { g_tot[gtid] = 0.0f; g_pos[gtid] = 0.0f; g_labels[gtid] = lab[gtid]; }
    if (gtid == 0) g_done = 0u;

    int row  = blockIdx.x * 8 + (threadIdx.x >> 5);
    int lane = threadIdx.x & 31;
    const float4* p = reinterpret_cast<const float4*>(inp + (size_t)row * D) + lane * 2;
    float4 a = p[0];
    float4 b = p[1];
    float ss = a.x*a.x + a.y*a.y + a.z*a.z + a.w*a.w
             + b.x*b.x + b.y*b.y + b.z*b.z + b.w*b.w;
    #pragma unroll
    for (int o = 16; o > 0; o >>= 1) ss += __shfl_xor_sync(0xffffffffu, ss, o);
    float scale = 1.0f / fmaxf(sqrtf(ss), 1e-12f);

    int bidx = row >> 7;
    int l    = row & 127;
    __nv_bfloat16* dst = (l == 0)
        ? (g_anchors + (size_t)bidx * D)
        : (g_rest + (size_t)(bidx * (SEQ - 1) + (l - 1)) * D);

    __nv_bfloat162 v0 = __floats2bfloat162_rn(a.x * scale, a.y * scale);
    __nv_bfloat162 v1 = __floats2bfloat162_rn(a.z * scale, a.w * scale);
    __nv_bfloat162 v2 = __floats2bfloat162_rn(b.x * scale, b.y * scale);
    __nv_bfloat162 v3 = __floats2bfloat162_rn(b.z * scale, b.w * scale);
    uint4 u;
    u.x = *reinterpret_cast<uint32_t*>(&v0);
    u.y = *reinterpret_cast<uint32_t*>(&v1);
    u.z = *reinterpret_cast<uint32_t*>(&v2);
    u.w = *reinterpret_cast<uint32_t*>(&v3);
    *reinterpret_cast<uint4*>(dst + lane * 8) = u;
}

// ---------------- kernel 2: fused GEMM + exp + row-sum + final reduce ----------------
__global__ void __launch_bounds__(256, 1) score_kernel(float* __restrict__ out) {
    extern __shared__ __align__(16) char S[];

    float* sTot    = reinterpret_cast<float*>(S + SM_MISC);
    float* sPos    = sTot + BM;
    int*   sRowLab = reinterpret_cast<int*>(sPos + BM);
    int*   sColLab = sRowLab + BM;
    int*   sFlag   = sColLab + BN;

    int tid  = threadIdx.x;
    int lane = tid & 31;
    int warp = tid >> 5;
    int wm = (warp & 1) * 64;   // 2 warps along M
    int wn = (warp >> 1) * 64;  // 4 warps along N
    int bm = blockIdx.x * BM;
    int bn = blockIdx.y * BN;

    if (tid < BM) {
        sTot[tid] = 0.0f;
        sPos[tid] = 0.0f;
        sRowLab[tid] = g_labels[bm + tid];
    }
    sColLab[tid] = g_collab[bn + tid];           // 256 cols, 256 threads

    const __nv_bfloat16* gA = g_anchors + (size_t)bm * D;
    const __nv_bfloat16* gB = g_rest    + (size_t)bn * D;
    uint32_t smA = smem_u32(S + SM_A);
    uint32_t smB = smem_u32(S + SM_B);

    // A: 128 rows x 8 chunks = 1024 -> 4/thread ; B: 256 x 8 = 2048 -> 8/thread
    #define ISSUE_TILE(kt_, st_)                                                   \
        do {                                                                       \
            int _ko = (kt_) * BK;                                                  \
            _Pragma("unroll")                                                      \
            for (int i = 0; i < 4; i++) {                                          \
                int idx = tid + i * 256;                                           \
                int r = idx >> 3, c = idx & 7;                                     \
                cp_async16(smA + (st_) * A_STAGE + (r * SSTRIDE + c * 8) * 2,      \
                           gA + (size_t)r * D + _ko + c * 8);                      \
            }                                                                      \
            _Pragma("unroll")                                                      \
            for (int i = 0; i < 8; i++) {                                          \
                int idx = tid + i * 256;                                           \
                int r = idx >> 3, c = idx & 7;                                     \
                cp_async16(smB + (st_) * B_STAGE + (r * SSTRIDE + c * 8) * 2,      \
                           gB + (size_t)r * D + _ko + c * 8);                      \
            }                                                                      \
            cp_commit();                                                           \
        } while (0)

    ISSUE_TILE(0, 0);
    ISSUE_TILE(1, 1);
    ISSUE_TILE(2, 2);

    float acc[4][8][4];
    #pragma unroll
    for (int mf = 0; mf < 4; mf++)
        #pragma unroll
        for (int nf = 0; nf < 8; nf++)
            #pragma unroll
            for (int r = 0; r < 4; r++) acc[mf][nf][r] = 0.0f;

    const __nv_bfloat16* sAp = reinterpret_cast<const __nv_bfloat16*>(S + SM_A);
    const __nv_bfloat16* sBp = reinterpret_cast<const __nv_bfloat16*>(S + SM_B);

    // fragment load (one k16 step) into register buffers
    #define LOAD_FRAGS(AF, BF, aBuf, bBuf, ks_)                                            \
        do {                                                                               \
            _Pragma("unroll")                                                              \
            for (int mf = 0; mf < 4; mf++) {                                               \
                uint32_t addr = smem_u32((aBuf) + (wm + mf * 16 + (lane & 15)) * SSTRIDE   \
                                              + (ks_) * 16 + (lane >> 4) * 8);             \
                asm volatile("ldmatrix.sync.aligned.m8n8.x4.shared.b16 {%0,%1,%2,%3}, [%4];" \
                             : "=r"((AF)[mf][0]), "=r"((AF)[mf][1]),                       \
                               "=r"((AF)[mf][2]), "=r"((AF)[mf][3])                        \
                             : "r"(addr));                                                 \
            }                                                                              \
            _Pragma("unroll")                                                              \
            for (int np = 0; np < 4; np++) {                                               \
                uint32_t addr = smem_u32((bBuf) + (wn + np * 16 + (lane >> 4) * 8 + (lane & 7)) * SSTRIDE \
                                              + (ks_) * 16 + ((lane >> 3) & 1) * 8);       \
                asm volatile("ldmatrix.sync.aligned.m8n8.x4.shared.b16 {%0,%1,%2,%3}, [%4];" \
                             : "=r"((BF)[2 * np][0]), "=r"((BF)[2 * np][1]),               \
                               "=r"((BF)[2 * np + 1][0]), "=r"((BF)[2 * np + 1][1])        \
                             : "r"(addr));                                                 \
            }                                                                              \
        } while (0)

    #define DO_MMAS(AF, BF)                                                                \
        do {                                                                               \
            _Pragma("unroll")                                                              \
            for (int mf = 0; mf < 4; mf++)                                                 \
                _Pragma("unroll")                                                          \
                for (int nf = 0; nf < 8; nf++)                                             \
                    asm volatile(                                                          \
                        "mma.sync.aligned.m16n8k16.row.col.f32.bf16.bf16.f32 "             \
                        "{%0,%1,%2,%3}, {%4,%5,%6,%7}, {%8,%9}, {%0,%1,%2,%3};"            \
                        : "+f"(acc[mf][nf][0]), "+f"(acc[mf][nf][1]),                      \
                          "+f"(acc[mf][nf][2]), "+f"(acc[mf][nf][3])                       \
                        : "r"((AF)[mf][0]), "r"((AF)[mf][1]),                              \
                          "r"((AF)[mf][2]), "r"((AF)[mf][3]),                              \
                          "r"((BF)[nf][0]), "r"((BF)[nf][1]));                             \
        } while (0)

    uint32_t afr0[4][4], bfr0[8][2], afr1[4][4], bfr1[8][2];

    #pragma unroll
    for (int kt = 0; kt < NKT; kt++) {
        if (kt == 0) cp_wait<2>();
        else if (kt == 1) cp_wait<2>();
        else if (kt == 2) cp_wait<1>();
        else cp_wait<0>();
        __syncthreads();

        const __nv_bfloat16* aBuf = sAp + (kt % 3) * (A_STAGE / 2);
        const __nv_bfloat16* bBuf = sBp + (kt % 3) * (B_STAGE / 2);

        // software-pipelined 4 k16 steps with register double buffering
        LOAD_FRAGS(afr0, bfr0, aBuf, bBuf, 0);
        LOAD_FRAGS(afr1, bfr1, aBuf, bBuf, 1);
        DO_MMAS(afr0, bfr0);
        LOAD_FRAGS(afr0, bfr0, aBuf, bBuf, 2);
        DO_MMAS(afr1, bfr1);
        LOAD_FRAGS(afr1, bfr1, aBuf, bBuf, 3);
        DO_MMAS(afr0, bfr0);
        DO_MMAS(afr1, bfr1);

        if (kt == 0) {
            __syncthreads();     // stage 0 fully consumed -> reuse for tile 3
            ISSUE_TILE(3, 0);
        }
    }

    // epilogue: exp + masked row-sums
    int qr = lane >> 2;
    int qc = (lane & 3) * 2;
    #pragma unroll
    for (int mf = 0; mf < 4; mf++) {
        #pragma unroll
        for (int h = 0; h < 2; h++) {
            int lrow = wm + mf * 16 + h * 8 + qr;
            int mylab = sRowLab[lrow];
            float ts = 0.0f, ps = 0.0f;
            #pragma unroll
            for (int nf = 0; nf < 8; nf++) {
                int c = wn + nf * 8 + qc;
                float e0 = __expf(acc[mf][nf][h * 2 + 0]);
                float e1 = __expf(acc[mf][nf][h * 2 + 1]);
                ts += e0 + e1;
                ps += (sColLab[c]     == mylab) ? e0 : 0.0f;
                ps += (sColLab[c + 1] == mylab) ? e1 : 0.0f;
            }
            ts += __shfl_xor_sync(0xffffffffu, ts, 1);
            ts += __shfl_xor_sync(0xffffffffu, ts, 2);
            ps += __shfl_xor_sync(0xffffffffu, ps, 1);
            ps += __shfl_xor_sync(0xffffffffu, ps, 2);
            if ((lane & 3) == 0) {
                atomicAdd(&sTot[lrow], ts);
                atomicAdd(&sPos[lrow], ps);
            }
        }
    }
    __syncthreads();
    if (tid < BM) {
        atomicAdd(&g_tot[bm + tid], sTot[tid]);
        atomicAdd(&g_pos[bm + tid], sPos[tid]);
    }

    // ---- fused finalize: last CTA computes the loss ----
    __threadfence();
    __syncthreads();
    if (tid == 0) {
        unsigned v = atomicAdd(&g_done, 1u);
        sFlag[0] = (v == TOTAL_BLOCKS - 1) ? 1 : 0;
    }
    __syncthreads();
    if (sFlag[0]) {
        __threadfence();
        float v = (logf(g_tot[tid]) - logf(g_pos[tid]))
                + (logf(g_tot[tid + 256]) - logf(g_pos[tid + 256]));
        #pragma unroll
        for (int o = 16; o > 0; o >>= 1) v += __shfl_xor_sync(0xffffffffu, v, o);
        float* red = sTot;   // reuse
        if (lane == 0) red[warp] = v;
        __syncthreads();
        if (tid == 0) {
            float s = 0.0f;
            #pragma unroll
            for (int w = 0; w < 8; w++) s += red[w];
            out[0] = s * (1.0f / 512.0f);
        }
    }
}

// ---------------- launch ----------------
extern "C" void kernel_launch(void* const* d_in, const int* in_sizes, int n_in,
                              void* d_out, int out_size) {
    const float* inp = (const float*)d_in[0];
    const int*   lab = (const int*)d_in[1];
    float*       out = (float*)d_out;

    cudaFuncSetAttribute(score_kernel, cudaFuncAttributeMaxDynamicSharedMemorySize, SM_TOTAL);

    normalize_kernel<<<(NB * SEQ) / 8, 256>>>(inp, lab);
    score_kernel<<<dim3(GRIDX, GRIDY), 256, SM_TOTAL>>>(out);
}

// round 7
// speedup vs baseline: 1.1909x; 1.1909x over previous
#include <cuda_runtime.h>
#include <cuda_bf16.h>
#include <cstdint>
#include <math.h>

#define NB 512
#define SEQ 128
#define D 256
#define NREST 65024            // NB*(SEQ-1)

#define BM 128
#define BN 128
#define BK 64
#define NKT (D / BK)           // 4
#define SSTRIDE 72             // bf16 elems; 144B row stride, conflict-free LDSM
#define STAGE_BYTES (BM * SSTRIDE * 2)       // 18432 per operand per stage
#define GRIDX 4                // anchor groups (NB/BM)
#define GRIDY (NREST / BN)     // 508
#define TOTAL_BLOCKS (GRIDX * GRIDY)

// dynamic smem layout (bytes): 3 A stages, 3 B stages, misc
#define SM_A 0
#define SM_B (3 * STAGE_BYTES)               // 55296
#define SM_MISC (6 * STAGE_BYTES)            // 110592
#define SM_TOTAL (SM_MISC + 4 * BM * 4 + 64)

// ---------------- device scratch ----------------
__device__ __nv_bfloat16 g_anchors[NB * D];
__device__ __nv_bfloat16 g_rest[(size_t)NREST * D];
__device__ int   g_labels[NB];
__device__ int   g_collab[NREST];
__device__ float g_tot[NB];
__device__ float g_pos[NB];
__device__ unsigned g_done;

__device__ __forceinline__ uint32_t smem_u32(const void* p) {
    return (uint32_t)__cvta_generic_to_shared(p);
}
__device__ __forceinline__ void cp_async16(uint32_t dst, const void* src) {
    asm volatile("cp.async.cg.shared.global [%0], [%1], 16;" :: "r"(dst), "l"(src) : "memory");
}
__device__ __forceinline__ void cp_commit() {
    asm volatile("cp.async.commit_group;" ::: "memory");
}
template <int N>
__device__ __forceinline__ void cp_wait() {
    asm volatile("cp.async.wait_group %0;" :: "n"(N) : "memory");
}

// ---------------- kernel 1: normalize + init ----------------
__global__ void normalize_kernel(const float* __restrict__ inp, const int* __restrict__ lab) {
    int gtid = blockIdx.x * 256 + threadIdx.x;
    if (gtid < NREST) g_collab[gtid] = lab[gtid / (SEQ - 1)];
    if (gtid < NB) { g_tot[gtid] = 0.0f; g_pos[gtid] = 0.0f; g_labels[gtid] = lab[gtid]; }
    if (gtid == 0) g_done = 0u;

    int row  = blockIdx.x * 8 + (threadIdx.x >> 5);
    int lane = threadIdx.x & 31;
    const float4* p = reinterpret_cast<const float4*>(inp + (size_t)row * D) + lane * 2;
    float4 a = p[0];
    float4 b = p[1];
    float ss = a.x*a.x + a.y*a.y + a.z*a.z + a.w*a.w
             + b.x*b.x + b.y*b.y + b.z*b.z + b.w*b.w;
    #pragma unroll
    for (int o = 16; o > 0; o >>= 1) ss += __shfl_xor_sync(0xffffffffu, ss, o);
    float scale = 1.0f / fmaxf(sqrtf(ss), 1e-12f);

    int bidx = row >> 7;
    int l    = row & 127;
    __nv_bfloat16* dst = (l == 0)
        ? (g_anchors + (size_t)bidx * D)
        : (g_rest + (size_t)(bidx * (SEQ - 1) + (l - 1)) * D);

    __nv_bfloat162 v0 = __floats2bfloat162_rn(a.x * scale, a.y * scale);
    __nv_bfloat162 v1 = __floats2bfloat162_rn(a.z * scale, a.w * scale);
    __nv_bfloat162 v2 = __floats2bfloat162_rn(b.x * scale, b.y * scale);
    __nv_bfloat162 v3 = __floats2bfloat162_rn(b.z * scale, b.w * scale);
    uint4 u;
    u.x = *reinterpret_cast<uint32_t*>(&v0);
    u.y = *reinterpret_cast<uint32_t*>(&v1);
    u.z = *reinterpret_cast<uint32_t*>(&v2);
    u.w = *reinterpret_cast<uint32_t*>(&v3);
    *reinterpret_cast<uint4*>(dst + lane * 8) = u;
}

// ---------------- kernel 2: fused GEMM + exp + row-sum + final reduce ----------------
__global__ void __launch_bounds__(256, 2) score_kernel(float* __restrict__ out) {
    extern __shared__ __align__(16) char S[];

    float* sTot    = reinterpret_cast<float*>(S + SM_MISC);
    float* sPos    = sTot + BM;
    int*   sRowLab = reinterpret_cast<int*>(sPos + BM);
    int*   sColLab = sRowLab + BM;
    int*   sFlag   = sColLab + BN;

    int tid  = threadIdx.x;
    int lane = tid & 31;
    int warp = tid >> 5;
    int wm = (warp & 3) * 32;   // 4 warps along M
    int wn = (warp >> 2) * 64;  // 2 warps along N
    int bm = blockIdx.x * BM;
    int bn = blockIdx.y * BN;

    if (tid < BM) {
        sTot[tid] = 0.0f;
        sPos[tid] = 0.0f;
        sRowLab[tid] = g_labels[bm + tid];
        sColLab[tid] = g_collab[bn + tid];
    }

    const __nv_bfloat16* gA = g_anchors + (size_t)bm * D;
    const __nv_bfloat16* gB = g_rest    + (size_t)bn * D;
    uint32_t smA = smem_u32(S + SM_A);
    uint32_t smB = smem_u32(S + SM_B);

    #define ISSUE_TILE(kt_, st_)                                                   \
        do {                                                                       \
            int _ko = (kt_) * BK;                                                  \
            _Pragma("unroll")                                                      \
            for (int i = 0; i < 4; i++) {                                          \
                int idx = tid + i * 256;                                           \
                int r = idx >> 3, c = idx & 7;                                     \
                uint32_t so = (st_) * STAGE_BYTES + (r * SSTRIDE + c * 8) * 2;     \
                cp_async16(smA + so, gA + (size_t)r * D + _ko + c * 8);            \
                cp_async16(smB + so, gB + (size_t)r * D + _ko + c * 8);            \
            }                                                                      \
            cp_commit();                                                           \
        } while (0)

    // prologue: tiles 0,1,2 -> stages 0,1,2
    ISSUE_TILE(0, 0);
    ISSUE_TILE(1, 1);
    ISSUE_TILE(2, 2);

    float acc[2][8][4];
    #pragma unroll
    for (int mf = 0; mf < 2; mf++)
        #pragma unroll
        for (int nf = 0; nf < 8; nf++)
            #pragma unroll
            for (int r = 0; r < 4; r++) acc[mf][nf][r] = 0.0f;

    const __nv_bfloat16* sAp = reinterpret_cast<const __nv_bfloat16*>(S + SM_A);
    const __nv_bfloat16* sBp = reinterpret_cast<const __nv_bfloat16*>(S + SM_B);

    // fragment load (one k16 step) into register buffers
    #define LOAD_FRAGS(AF, BF, aBuf, bBuf, ks_)                                            \
        do {                                                                               \
            _Pragma("unroll")                                                              \
            for (int mf = 0; mf < 2; mf++) {                                               \
                uint32_t addr = smem_u32((aBuf) + (wm + mf * 16 + (lane & 15)) * SSTRIDE   \
                                              + (ks_) * 16 + (lane >> 4) * 8);             \
                asm volatile("ldmatrix.sync.aligned.m8n8.x4.shared.b16 {%0,%1,%2,%3}, [%4];" \
                             : "=r"((AF)[mf][0]), "=r"((AF)[mf][1]),                       \
                               "=r"((AF)[mf][2]), "=r"((AF)[mf][3])                        \
                             : "r"(addr));                                                 \
            }                                                                              \
            _Pragma("unroll")                                                              \
            for (int np = 0; np < 4; np++) {                                               \
                uint32_t addr = smem_u32((bBuf) + (wn + np * 16 + (lane >> 4) * 8 + (lane & 7)) * SSTRIDE \
                                              + (ks_) * 16 + ((lane >> 3) & 1) * 8);       \
                asm volatile("ldmatrix.sync.aligned.m8n8.x4.shared.b16 {%0,%1,%2,%3}, [%4];" \
                             : "=r"((BF)[2 * np][0]), "=r"((BF)[2 * np][1]),               \
                               "=r"((BF)[2 * np + 1][0]), "=r"((BF)[2 * np + 1][1])        \
                             : "r"(addr));                                                 \
            }                                                                              \
        } while (0)

    #define DO_MMAS(AF, BF)                                                                \
        do {                                                                               \
            _Pragma("unroll")                                                              \
            for (int mf = 0; mf < 2; mf++)                                                 \
                _Pragma("unroll")                                                          \
                for (int nf = 0; nf < 8; nf++)                                             \
                    asm volatile(                                                          \
                        "mma.sync.aligned.m16n8k16.row.col.f32.bf16.bf16.f32 "             \
                        "{%0,%1,%2,%3}, {%4,%5,%6,%7}, {%8,%9}, {%0,%1,%2,%3};"            \
                        : "+f"(acc[mf][nf][0]), "+f"(acc[mf][nf][1]),                      \
                          "+f"(acc[mf][nf][2]), "+f"(acc[mf][nf][3])                       \
                        : "r"((AF)[mf][0]), "r"((AF)[mf][1]),                              \
                          "r"((AF)[mf][2]), "r"((AF)[mf][3]),                              \
                          "r"((BF)[nf][0]), "r"((BF)[nf][1]));                             \
        } while (0)

    uint32_t afr0[2][4], bfr0[8][2], afr1[2][4], bfr1[8][2];

    #pragma unroll
    for (int kt = 0; kt < NKT; kt++) {
        if (kt == 0) cp_wait<2>();
        else if (kt == 1) cp_wait<2>();
        else if (kt == 2) cp_wait<1>();
        else cp_wait<0>();
        __syncthreads();

        const __nv_bfloat16* aBuf = sAp + (kt % 3) * (STAGE_BYTES / 2);
        const __nv_bfloat16* bBuf = sBp + (kt % 3) * (STAGE_BYTES / 2);

        // software-pipelined k16 steps: LDSM(ks+1) issued before HMMA burst of ks
        LOAD_FRAGS(afr0, bfr0, aBuf, bBuf, 0);
        LOAD_FRAGS(afr1, bfr1, aBuf, bBuf, 1);
        DO_MMAS(afr0, bfr0);
        LOAD_FRAGS(afr0, bfr0, aBuf, bBuf, 2);
        DO_MMAS(afr1, bfr1);
        LOAD_FRAGS(afr1, bfr1, aBuf, bBuf, 3);
        DO_MMAS(afr0, bfr0);

        if (kt == 0) {
            // stage 0 fully consumed (all reads for kt=0 done) -> reuse for tile 3
            __syncthreads();
            ISSUE_TILE(3, 0);
        }
        DO_MMAS(afr1, bfr1);
    }

    // epilogue: exp + masked row-sums
    int qr = lane >> 2;
    int qc = (lane & 3) * 2;
    #pragma unroll
    for (int mf = 0; mf < 2; mf++) {
        #pragma unroll
        for (int h = 0; h < 2; h++) {
            int lrow = wm + mf * 16 + h * 8 + qr;
            int mylab = sRowLab[lrow];
            float ts = 0.0f, ps = 0.0f;
            #pragma unroll
            for (int nf = 0; nf < 8; nf++) {
                int c = wn + nf * 8 + qc;
                float e0 = __expf(acc[mf][nf][h * 2 + 0]);
                float e1 = __expf(acc[mf][nf][h * 2 + 1]);
                ts += e0 + e1;
                ps += (sColLab[c]     == mylab) ? e0 : 0.0f;
                ps += (sColLab[c + 1] == mylab) ? e1 : 0.0f;
            }
            ts += __shfl_xor_sync(0xffffffffu, ts, 1);
            ts += __shfl_xor_sync(0xffffffffu, ts, 2);
            ps += __shfl_xor_sync(0xffffffffu, ps, 1);
            ps += __shfl_xor_sync(0xffffffffu, ps, 2);
            if ((lane & 3) == 0) {
                atomicAdd(&sTot[lrow], ts);
                atomicAdd(&sPos[lrow], ps);
            }
        }
    }
    __syncthreads();
    if (tid < BM) {
        atomicAdd(&g_tot[bm + tid], sTot[tid]);
        atomicAdd(&g_pos[bm + tid], sPos[tid]);
    }

    // ---- fused finalize: last CTA computes the loss ----
    __threadfence();
    __syncthreads();
    if (tid == 0) {
        unsigned v = atomicAdd(&g_done, 1u);
        sFlag[0] = (v == TOTAL_BLOCKS - 1) ? 1 : 0;
    }
    __syncthreads();
    if (sFlag[0]) {
        __threadfence();
        float v = (logf(g_tot[tid]) - logf(g_pos[tid]))
                + (logf(g_tot[tid + 256]) - logf(g_pos[tid + 256]));
        #pragma unroll
        for (int o = 16; o > 0; o >>= 1) v += __shfl_xor_sync(0xffffffffu, v, o);
        float* red = sTot;   // reuse
        if (lane == 0) red[warp] = v;
        __syncthreads();
        if (tid == 0) {
            float s = 0.0f;
            #pragma unroll
            for (int w = 0; w < 8; w++) s += red[w];
            out[0] = s * (1.0f / 512.0f);
        }
    }
}

// ---------------- launch ----------------
extern "C" void kernel_launch(void* const* d_in, const int* in_sizes, int n_in,
                              void* d_out, int out_size) {
    const float* inp = (const float*)d_in[0];
    const int*   lab = (const int*)d_in[1];
    float*       out = (float*)d_out;

    cudaFuncSetAttribute(score_kernel, cudaFuncAttributeMaxDynamicSharedMemorySize, SM_TOTAL);

    normalize_kernel<<<(NB * SEQ) / 8, 256>>>(inp, lab);
    score_kernel<<<dim3(GRIDX, GRIDY), 256, SM_TOTAL>>>(out);
}

// round 8
// speedup vs baseline: 1.2311x; 1.0338x over previous
#include <cuda_runtime.h>
#include <cuda_bf16.h>
#include <cuda_fp8.h>
#include <cstdint>
#include <math.h>

#define NB 512
#define SEQ 128
#define D 256
#define NREST 65024            // NB*(SEQ-1)

#define BM 128
#define BN 128
#define GRIDX 4                // NB/BM
#define GRIDY (NREST / BN)     // 508
#define TOTAL_BLOCKS (GRIDX * GRIDY)

#define SROW 272               // bytes per smem row: 256 fp8 + 16 pad (conflict-free LDSM)
#define A_BYTES (BM * SROW)    // 34816
#define B_BYTES (BN * SROW)    // 34816

// dynamic smem layout (bytes)
#define SM_A 0
#define SM_B A_BYTES
#define SM_MISC (A_BYTES + B_BYTES)          // 69632
#define SM_TOTAL (SM_MISC + 4 * BM * 4 + 64)

// ---------------- device scratch ----------------
__device__ uint8_t g_anchors[NB * D];        // e4m3
__device__ uint8_t g_rest[(size_t)NREST * D];
__device__ int   g_labels[NB];
__device__ int   g_collab[NREST];
__device__ float g_tot[NB];
__device__ float g_pos[NB];
__device__ unsigned g_done;

__device__ __forceinline__ uint32_t smem_u32(const void* p) {
    return (uint32_t)__cvta_generic_to_shared(p);
}
__device__ __forceinline__ void cp_async16(uint32_t dst, const void* src) {
    asm volatile("cp.async.cg.shared.global [%0], [%1], 16;" :: "r"(dst), "l"(src) : "memory");
}
__device__ __forceinline__ void cp_commit() {
    asm volatile("cp.async.commit_group;" ::: "memory");
}
__device__ __forceinline__ void cp_wait0() {
    asm volatile("cp.async.wait_group 0;" ::: "memory");
}

// ---------------- kernel 1: normalize + init, write e4m3 ----------------
__global__ void normalize_kernel(const float* __restrict__ inp, const int* __restrict__ lab) {
    int gtid = blockIdx.x * 256 + threadIdx.x;
    if (gtid < NREST) g_collab[gtid] = lab[gtid / (SEQ - 1)];
    if (gtid < NB) { g_tot[gtid] = 0.0f; g_pos[gtid] = 0.0f; g_labels[gtid] = lab[gtid]; }
    if (gtid == 0) g_done = 0u;

    int row  = blockIdx.x * 8 + (threadIdx.x >> 5);
    int lane = threadIdx.x & 31;
    const float4* p = reinterpret_cast<const float4*>(inp + (size_t)row * D) + lane * 2;
    float4 a = p[0];
    float4 b = p[1];
    float ss = a.x*a.x + a.y*a.y + a.z*a.z + a.w*a.w
             + b.x*b.x + b.y*b.y + b.z*b.z + b.w*b.w;
    #pragma unroll
    for (int o = 16; o > 0; o >>= 1) ss += __shfl_xor_sync(0xffffffffu, ss, o);
    float scale = 1.0f / fmaxf(sqrtf(ss), 1e-12f);

    int bidx = row >> 7;
    int l    = row & 127;
    uint8_t* dst = (l == 0)
        ? (g_anchors + (size_t)bidx * D)
        : (g_rest + (size_t)(bidx * (SEQ - 1) + (l - 1)) * D);

    __nv_fp8x2_storage_t q0 = __nv_cvt_float2_to_fp8x2(
        make_float2(a.x * scale, a.y * scale), __NV_SATFINITE, __NV_E4M3);
    __nv_fp8x2_storage_t q1 = __nv_cvt_float2_to_fp8x2(
        make_float2(a.z * scale, a.w * scale), __NV_SATFINITE, __NV_E4M3);
    __nv_fp8x2_storage_t q2 = __nv_cvt_float2_to_fp8x2(
        make_float2(b.x * scale, b.y * scale), __NV_SATFINITE, __NV_E4M3);
    __nv_fp8x2_storage_t q3 = __nv_cvt_float2_to_fp8x2(
        make_float2(b.z * scale, b.w * scale), __NV_SATFINITE, __NV_E4M3);
    uint2 u;
    u.x = (uint32_t)q0 | ((uint32_t)q1 << 16);
    u.y = (uint32_t)q2 | ((uint32_t)q3 << 16);
    *reinterpret_cast<uint2*>(dst + lane * 8) = u;
}

// ---------------- kernel 2: FP8 GEMM + exp + row-sum + final reduce ----------------
__global__ void __launch_bounds__(256, 2) score_kernel(float* __restrict__ out) {
    extern __shared__ __align__(16) char S[];

    float* sTot    = reinterpret_cast<float*>(S + SM_MISC);
    float* sPos    = sTot + BM;
    int*   sRowLab = reinterpret_cast<int*>(sPos + BM);
    int*   sColLab = sRowLab + BM;
    int*   sFlag   = sColLab + BN;

    int tid  = threadIdx.x;
    int lane = tid & 31;
    int warp = tid >> 5;
    int wm = (warp & 3) * 32;   // 4 warps along M
    int wn = (warp >> 2) * 64;  // 2 warps along N
    int bm = blockIdx.x * BM;
    int bn = blockIdx.y * BN;

    if (tid < BM) {
        sTot[tid] = 0.0f;
        sPos[tid] = 0.0f;
        sRowLab[tid] = g_labels[bm + tid];
        sColLab[tid] = g_collab[bn + tid];
    }

    // load full tiles: 128 rows x 256B each; 16 chunks of 16B per row -> 8 per thread per operand
    const uint8_t* gA = g_anchors + (size_t)bm * D;
    const uint8_t* gB = g_rest    + (size_t)bn * D;
    uint32_t smA = smem_u32(S + SM_A);
    uint32_t smB = smem_u32(S + SM_B);
    #pragma unroll
    for (int i = 0; i < 8; i++) {
        int idx = tid + i * 256;
        int r = idx >> 4, c = idx & 15;
        cp_async16(smA + r * SROW + c * 16, gA + (size_t)r * D + c * 16);
        cp_async16(smB + r * SROW + c * 16, gB + (size_t)r * D + c * 16);
    }
    cp_commit();

    float acc[2][8][4];
    #pragma unroll
    for (int mf = 0; mf < 2; mf++)
        #pragma unroll
        for (int nf = 0; nf < 8; nf++)
            #pragma unroll
            for (int r = 0; r < 4; r++) acc[mf][nf][r] = 0.0f;

    // fragment load for one k32 step (32 bytes of K); b16-pair view of fp8 data
    #define LOAD_FRAGS(AF, BF, ks_)                                                        \
        do {                                                                               \
            _Pragma("unroll")                                                              \
            for (int mf = 0; mf < 2; mf++) {                                               \
                uint32_t addr = smA + (wm + mf * 16 + (lane & 15)) * SROW                  \
                                    + (ks_) * 32 + (lane >> 4) * 16;                       \
                asm volatile("ldmatrix.sync.aligned.m8n8.x4.shared.b16 {%0,%1,%2,%3}, [%4];" \
                             : "=r"((AF)[mf][0]), "=r"((AF)[mf][1]),                       \
                               "=r"((AF)[mf][2]), "=r"((AF)[mf][3])                        \
                             : "r"(addr));                                                 \
            }                                                                              \
            _Pragma("unroll")                                                              \
            for (int np = 0; np < 4; np++) {                                               \
                uint32_t addr = smB + (wn + np * 16 + (lane >> 4) * 8 + (lane & 7)) * SROW \
                                    + (ks_) * 32 + ((lane >> 3) & 1) * 16;                 \
                asm volatile("ldmatrix.sync.aligned.m8n8.x4.shared.b16 {%0,%1,%2,%3}, [%4];" \
                             : "=r"((BF)[2 * np][0]), "=r"((BF)[2 * np][1]),               \
                               "=r"((BF)[2 * np + 1][0]), "=r"((BF)[2 * np + 1][1])        \
                             : "r"(addr));                                                 \
            }                                                                              \
        } while (0)

    #define DO_MMAS(AF, BF)                                                                \
        do {                                                                               \
            _Pragma("unroll")                                                              \
            for (int mf = 0; mf < 2; mf++)                                                 \
                _Pragma("unroll")                                                          \
                for (int nf = 0; nf < 8; nf++)                                             \
                    asm volatile(                                                          \
                        "mma.sync.aligned.m16n8k32.row.col.f32.e4m3.e4m3.f32 "             \
                        "{%0,%1,%2,%3}, {%4,%5,%6,%7}, {%8,%9}, {%0,%1,%2,%3};"            \
                        : "+f"(acc[mf][nf][0]), "+f"(acc[mf][nf][1]),                      \
                          "+f"(acc[mf][nf][2]), "+f"(acc[mf][nf][3])                       \
                        : "r"((AF)[mf][0]), "r"((AF)[mf][1]),                              \
                          "r"((AF)[mf][2]), "r"((AF)[mf][3]),                              \
                          "r"((BF)[nf][0]), "r"((BF)[nf][1]));                             \
        } while (0)

    uint32_t afr0[2][4], bfr0[8][2], afr1[2][4], bfr1[8][2];

    cp_wait0();
    __syncthreads();

    // 8 k32 steps, register ping-pong: LDSM(ks+1) issued before MMA burst of ks
    LOAD_FRAGS(afr0, bfr0, 0);
    LOAD_FRAGS(afr1, bfr1, 1);
    DO_MMAS(afr0, bfr0);
    LOAD_FRAGS(afr0, bfr0, 2);
    DO_MMAS(afr1, bfr1);
    LOAD_FRAGS(afr1, bfr1, 3);
    DO_MMAS(afr0, bfr0);
    LOAD_FRAGS(afr0, bfr0, 4);
    DO_MMAS(afr1, bfr1);
    LOAD_FRAGS(afr1, bfr1, 5);
    DO_MMAS(afr0, bfr0);
    LOAD_FRAGS(afr0, bfr0, 6);
    DO_MMAS(afr1, bfr1);
    LOAD_FRAGS(afr1, bfr1, 7);
    DO_MMAS(afr0, bfr0);
    DO_MMAS(afr1, bfr1);

    // epilogue: exp + masked row-sums
    int qr = lane >> 2;
    int qc = (lane & 3) * 2;
    #pragma unroll
    for (int mf = 0; mf < 2; mf++) {
        #pragma unroll
        for (int h = 0; h < 2; h++) {
            int lrow = wm + mf * 16 + h * 8 + qr;
            int mylab = sRowLab[lrow];
            float ts = 0.0f, ps = 0.0f;
            #pragma unroll
            for (int nf = 0; nf < 8; nf++) {
                int c = wn + nf * 8 + qc;
                float e0 = __expf(acc[mf][nf][h * 2 + 0]);
                float e1 = __expf(acc[mf][nf][h * 2 + 1]);
                ts += e0 + e1;
                ps += (sColLab[c]     == mylab) ? e0 : 0.0f;
                ps += (sColLab[c + 1] == mylab) ? e1 : 0.0f;
            }
            ts += __shfl_xor_sync(0xffffffffu, ts, 1);
            ts += __shfl_xor_sync(0xffffffffu, ts, 2);
            ps += __shfl_xor_sync(0xffffffffu, ps, 1);
            ps += __shfl_xor_sync(0xffffffffu, ps, 2);
            if ((lane & 3) == 0) {
                atomicAdd(&sTot[lrow], ts);
                atomicAdd(&sPos[lrow], ps);
            }
        }
    }
    __syncthreads();
    if (tid < BM) {
        atomicAdd(&g_tot[bm + tid], sTot[tid]);
        atomicAdd(&g_pos[bm + tid], sPos[tid]);
    }

    // ---- fused finalize: last CTA computes the loss ----
    __threadfence();
    __syncthreads();
    if (tid == 0) {
        unsigned v = atomicAdd(&g_done, 1u);
        sFlag[0] = (v == TOTAL_BLOCKS - 1) ? 1 : 0;
    }
    __syncthreads();
    if (sFlag[0]) {
        __threadfence();
        float v = (logf(g_tot[tid]) - logf(g_pos[tid]))
                + (logf(g_tot[tid + 256]) - logf(g_pos[tid + 256]));
        #pragma unroll
        for (int o = 16; o > 0; o >>= 1) v += __shfl_xor_sync(0xffffffffu, v, o);
        float* red = sTot;   // reuse
        if (lane == 0) red[warp] = v;
        __syncthreads();
        if (tid == 0) {
            float s = 0.0f;
            #pragma unroll
            for (int w = 0; w < 8; w++) s += red[w];
            out[0] = s * (1.0f / 512.0f);
        }
    }
}

// ---------------- launch ----------------
extern "C" void kernel_launch(void* const* d_in, const int* in_sizes, int n_in,
                              void* d_out, int out_size) {
    const float* inp = (const float*)d_in[0];
    const int*   lab = (const int*)d_in[1];
    float*       out = (float*)d_out;

    cudaFuncSetAttribute(score_kernel, cudaFuncAttributeMaxDynamicSharedMemorySize, SM_TOTAL);

    normalize_kernel<<<(NB * SEQ) / 8, 256>>>(inp, lab);
    score_kernel<<<dim3(GRIDX, GRIDY), 256, SM_TOTAL>>>(out);
}

// round 9
// speedup vs baseline: 1.2958x; 1.0525x over previous
#include <cuda_runtime.h>
#include <cuda_bf16.h>
#include <cuda_fp8.h>
#include <cstdint>
#include <math.h>

#define NB 512
#define SEQ 128
#define D 256
#define NREST 65024            // NB*(SEQ-1)

#define BM 128
#define BN 128
#define GRIDX 4                // NB/BM
#define GRIDY 74               // persistent: 4*74 = 296 CTAs = 2/SM
#define NTILES (NREST / BN)    // 508
#define TOTAL_BLOCKS (GRIDX * GRIDY)

#define SROW 272               // bytes per smem row: 256 fp8 + 16 pad (conflict-free LDSM)
#define TILE_BYTES (128 * SROW)   // 34816

// dynamic smem layout (bytes)
#define SM_A 0
#define SM_B TILE_BYTES                       // two stages: + (t&1)*TILE_BYTES
#define SM_CLAB (SM_B + 2 * TILE_BYTES)       // int collab[2][128]
#define SM_MISC (SM_CLAB + 2 * BN * 4)
#define SM_TOTAL (SM_MISC + 3 * BM * 4 + 64)

// ---------------- device scratch ----------------
__device__ uint8_t g_anchors[NB * D];        // e4m3
__device__ uint8_t g_rest[(size_t)NREST * D];
__device__ int   g_labels[NB];
__device__ int   g_collab[NREST];
__device__ float g_tot[NB];
__device__ float g_pos[NB];
__device__ unsigned g_done;

__device__ __forceinline__ uint32_t smem_u32(const void* p) {
    return (uint32_t)__cvta_generic_to_shared(p);
}
__device__ __forceinline__ void cp_async16(uint32_t dst, const void* src) {
    asm volatile("cp.async.cg.shared.global [%0], [%1], 16;" :: "r"(dst), "l"(src) : "memory");
}
__device__ __forceinline__ void cp_commit() {
    asm volatile("cp.async.commit_group;" ::: "memory");
}
template <int N>
__device__ __forceinline__ void cp_wait() {
    asm volatile("cp.async.wait_group %0;" :: "n"(N) : "memory");
}

// ---------------- kernel 1: normalize + init, write e4m3 ----------------
__global__ void normalize_kernel(const float* __restrict__ inp, const int* __restrict__ lab) {
    int gtid = blockIdx.x * 256 + threadIdx.x;
    if (gtid < NREST) g_collab[gtid] = lab[gtid / (SEQ - 1)];
    if (gtid < NB) { g_tot[gtid] = 0.0f; g_pos[gtid] = 0.0f; g_labels[gtid] = lab[gtid]; }
    if (gtid == 0) g_done = 0u;

    int row  = blockIdx.x * 8 + (threadIdx.x >> 5);
    int lane = threadIdx.x & 31;
    const float4* p = reinterpret_cast<const float4*>(inp + (size_t)row * D) + lane * 2;
    float4 a = p[0];
    float4 b = p[1];
    float ss = a.x*a.x + a.y*a.y + a.z*a.z + a.w*a.w
             + b.x*b.x + b.y*b.y + b.z*b.z + b.w*b.w;
    #pragma unroll
    for (int o = 16; o > 0; o >>= 1) ss += __shfl_xor_sync(0xffffffffu, ss, o);
    float scale = 1.0f / fmaxf(sqrtf(ss), 1e-12f);

    int bidx = row >> 7;
    int l    = row & 127;
    uint8_t* dst = (l == 0)
        ? (g_anchors + (size_t)bidx * D)
        : (g_rest + (size_t)(bidx * (SEQ - 1) + (l - 1)) * D);

    __nv_fp8x2_storage_t q0 = __nv_cvt_float2_to_fp8x2(
        make_float2(a.x * scale, a.y * scale), __NV_SATFINITE, __NV_E4M3);
    __nv_fp8x2_storage_t q1 = __nv_cvt_float2_to_fp8x2(
        make_float2(a.z * scale, a.w * scale), __NV_SATFINITE, __NV_E4M3);
    __nv_fp8x2_storage_t q2 = __nv_cvt_float2_to_fp8x2(
        make_float2(b.x * scale, b.y * scale), __NV_SATFINITE, __NV_E4M3);
    __nv_fp8x2_storage_t q3 = __nv_cvt_float2_to_fp8x2(
        make_float2(b.z * scale, b.w * scale), __NV_SATFINITE, __NV_E4M3);
    uint2 u;
    u.x = (uint32_t)q0 | ((uint32_t)q1 << 16);
    u.y = (uint32_t)q2 | ((uint32_t)q3 << 16);
    *reinterpret_cast<uint2*>(dst + lane * 8) = u;
}

// ---------------- kernel 2: persistent FP8 GEMM + exp + row-sum + final reduce --------
__global__ void __launch_bounds__(256, 2) score_kernel(float* __restrict__ out) {
    extern __shared__ __align__(16) char S[];

    int*   sColLab = reinterpret_cast<int*>(S + SM_CLAB);  // [2][128]
    float* sTot    = reinterpret_cast<float*>(S + SM_MISC);
    float* sPos    = sTot + BM;
    int*   sFlag   = reinterpret_cast<int*>(sPos + BM);

    int tid  = threadIdx.x;
    int lane = tid & 31;
    int warp = tid >> 5;
    int wm = (warp & 3) * 32;   // 4 warps along M
    int wn = (warp >> 2) * 64;  // 2 warps along N
    int bm = blockIdx.x * BM;
    int gy = blockIdx.y;
    int T  = (NTILES - gy + GRIDY - 1) / GRIDY;   // 7 (gy<64) or 6

    if (tid < BM) { sTot[tid] = 0.0f; sPos[tid] = 0.0f; }

    const uint8_t* gA = g_anchors + (size_t)bm * D;
    uint32_t smA = smem_u32(S + SM_A);
    uint32_t smB = smem_u32(S + SM_B);
    uint32_t smC = smem_u32(S + SM_CLAB);

    // B tile load: 128 rows x 256B = 2048 16B-chunks -> 8/thread ; + 128 collab ints (512B)
    #define ISSUE_B(t_, st_)                                                        \
        do {                                                                        \
            int _bn = (gy + (t_) * GRIDY) * BN;                                     \
            const uint8_t* _gB = g_rest + (size_t)_bn * D;                          \
            _Pragma("unroll")                                                       \
            for (int i = 0; i < 8; i++) {                                           \
                int idx = tid + i * 256;                                            \
                int r = idx >> 4, c = idx & 15;                                     \
                cp_async16(smB + (st_) * TILE_BYTES + r * SROW + c * 16,            \
                           _gB + (size_t)r * D + c * 16);                           \
            }                                                                       \
            if (tid < 32)                                                           \
                cp_async16(smC + (st_) * 512 + tid * 16,                            \
                           g_collab + _bn + tid * 4);                               \
            cp_commit();                                                            \
        } while (0)

    // prologue: A + B0 in group 0; B1 in group 1
    #pragma unroll
    for (int i = 0; i < 8; i++) {
        int idx = tid + i * 256;
        int r = idx >> 4, c = idx & 15;
        cp_async16(smA + r * SROW + c * 16, gA + (size_t)r * D + c * 16);
    }
    ISSUE_B(0, 0);        // commits group 0 (A + B0)
    ISSUE_B(1, 1);        // group 1

    // row labels fixed per thread for the whole kernel
    int qr = lane >> 2;
    int qc = (lane & 3) * 2;
    int rlab[2][2];
    #pragma unroll
    for (int mf = 0; mf < 2; mf++)
        #pragma unroll
        for (int h = 0; h < 2; h++)
            rlab[mf][h] = g_labels[bm + wm + mf * 16 + h * 8 + qr];

    float rts[2][2] = {{0.f, 0.f}, {0.f, 0.f}};
    float rps[2][2] = {{0.f, 0.f}, {0.f, 0.f}};

    uint32_t afr[2][4], bfr[8][2];

    for (int t = 0; t < T; t++) {
        if (t + 1 < T) cp_wait<1>(); else cp_wait<0>();
        __syncthreads();

        uint32_t bBase = smB + (t & 1) * TILE_BYTES;

        float acc[2][8][4];
        #pragma unroll
        for (int mf = 0; mf < 2; mf++)
            #pragma unroll
            for (int nf = 0; nf < 8; nf++)
                #pragma unroll
                for (int r = 0; r < 4; r++) acc[mf][nf][r] = 0.0f;

        #pragma unroll
        for (int ks = 0; ks < 8; ks++) {
            #pragma unroll
            for (int mf = 0; mf < 2; mf++) {
                uint32_t addr = smA + (wm + mf * 16 + (lane & 15)) * SROW
                                    + ks * 32 + (lane >> 4) * 16;
                asm volatile("ldmatrix.sync.aligned.m8n8.x4.shared.b16 {%0,%1,%2,%3}, [%4];"
                             : "=r"(afr[mf][0]), "=r"(afr[mf][1]),
                               "=r"(afr[mf][2]), "=r"(afr[mf][3])
                             : "r"(addr));
            }
            #pragma unroll
            for (int np = 0; np < 4; np++) {
                uint32_t addr = bBase + (wn + np * 16 + (lane >> 4) * 8 + (lane & 7)) * SROW
                                      + ks * 32 + ((lane >> 3) & 1) * 16;
                asm volatile("ldmatrix.sync.aligned.m8n8.x4.shared.b16 {%0,%1,%2,%3}, [%4];"
                             : "=r"(bfr[2 * np][0]), "=r"(bfr[2 * np][1]),
                               "=r"(bfr[2 * np + 1][0]), "=r"(bfr[2 * np + 1][1])
                             : "r"(addr));
            }
            #pragma unroll
            for (int mf = 0; mf < 2; mf++)
                #pragma unroll
                for (int nf = 0; nf < 8; nf++)
                    asm volatile(
                        "mma.sync.aligned.m16n8k32.row.col.f32.e4m3.e4m3.f32 "
                        "{%0,%1,%2,%3}, {%4,%5,%6,%7}, {%8,%9}, {%0,%1,%2,%3};"
                        : "+f"(acc[mf][nf][0]), "+f"(acc[mf][nf][1]),
                          "+f"(acc[mf][nf][2]), "+f"(acc[mf][nf][3])
                        : "r"(afr[mf][0]), "r"(afr[mf][1]), "r"(afr[mf][2]), "r"(afr[mf][3]),
                          "r"(bfr[nf][0]), "r"(bfr[nf][1]));
        }

        // epilogue for tile t: exp + masked sums into per-thread row accumulators
        const int* clab = sColLab + (t & 1) * BN;
        #pragma unroll
        for (int mf = 0; mf < 2; mf++) {
            #pragma unroll
            for (int h = 0; h < 2; h++) {
                int mylab = rlab[mf][h];
                float ts = 0.0f, ps = 0.0f;
                #pragma unroll
                for (int nf = 0; nf < 8; nf++) {
                    int c = wn + nf * 8 + qc;
                    float e0 = __expf(acc[mf][nf][h * 2 + 0]);
                    float e1 = __expf(acc[mf][nf][h * 2 + 1]);
                    ts += e0 + e1;
                    ps += (clab[c]     == mylab) ? e0 : 0.0f;
                    ps += (clab[c + 1] == mylab) ? e1 : 0.0f;
                }
                ts += __shfl_xor_sync(0xffffffffu, ts, 1);
                ts += __shfl_xor_sync(0xffffffffu, ts, 2);
                ps += __shfl_xor_sync(0xffffffffu, ps, 1);
                ps += __shfl_xor_sync(0xffffffffu, ps, 2);
                if ((lane & 3) == 0) {
                    rts[mf][h] += ts;
                    rps[mf][h] += ps;
                }
            }
        }

        // stage (t&1) fully consumed (MMA frags in regs, collab read) -> refill
        __syncthreads();
        if (t + 2 < T) ISSUE_B(t + 2, t & 1);
    }

    // drain per-thread accumulators -> smem -> global
    if ((lane & 3) == 0) {
        #pragma unroll
        for (int mf = 0; mf < 2; mf++)
            #pragma unroll
            for (int h = 0; h < 2; h++) {
                int lrow = wm + mf * 16 + h * 8 + qr;
                atomicAdd(&sTot[lrow], rts[mf][h]);
                atomicAdd(&sPos[lrow], rps[mf][h]);
            }
    }
    __syncthreads();
    if (tid < BM) {
        atomicAdd(&g_tot[bm + tid], sTot[tid]);
        atomicAdd(&g_pos[bm + tid], sPos[tid]);
    }

    // ---- fused finalize: last CTA computes the loss ----
    __threadfence();
    __syncthreads();
    if (tid == 0) {
        unsigned v = atomicAdd(&g_done, 1u);
        sFlag[0] = (v == TOTAL_BLOCKS - 1) ? 1 : 0;
    }
    __syncthreads();
    if (sFlag[0]) {
        __threadfence();
        float v = (logf(g_tot[tid]) - logf(g_pos[tid]))
                + (logf(g_tot[tid + 256]) - logf(g_pos[tid + 256]));
        #pragma unroll
        for (int o = 16; o > 0; o >>= 1) v += __shfl_xor_sync(0xffffffffu, v, o);
        float* red = sTot;   // reuse
        if (lane == 0) red[warp] = v;
        __syncthreads();
        if (tid == 0) {
            float s = 0.0f;
            #pragma unroll
            for (int w = 0; w < 8; w++) s += red[w];
            out[0] = s * (1.0f / 512.0f);
        }
    }
}

// ---------------- launch ----------------
extern "C" void kernel_launch(void* const* d_in, const int* in_sizes, int n_in,
                              void* d_out, int out_size) {
    const float* inp = (const float*)d_in[0];
    const int*   lab = (const int*)d_in[1];
    float*       out = (float*)d_out;

    cudaFuncSetAttribute(score_kernel, cudaFuncAttributeMaxDynamicSharedMemorySize, SM_TOTAL);

    normalize_kernel<<<(NB * SEQ) / 8, 256>>>(inp, lab);
    score_kernel<<<dim3(GRIDX, GRIDY), 256, SM_TOTAL>>>(out);
}

// round 10
// speedup vs baseline: 1.3354x; 1.0306x over previous
#include <cuda_runtime.h>
#include <cuda_bf16.h>
#include <cuda_fp8.h>
#include <cstdint>
#include <math.h>

#define NB 512
#define SEQ 128
#define D 256
#define NREST 65024            // NB*(SEQ-1)

#define BM 128
#define BROWS 127              // real columns per tile = one batch of rest rows
#define GRIDX 4                // NB/BM
#define GRIDY 74               // persistent: 4*74 = 296 CTAs = 2/SM
#define NTILES NB              // 512 tiles, one per batch
#define TOTAL_BLOCKS (GRIDX * GRIDY)

#define SROW 272               // bytes per smem row: 256 fp8 + 16 pad (conflict-free LDSM)
#define TILE_BYTES (128 * SROW)   // 34816 (includes zero pad row 127)

// dynamic smem layout (bytes)
#define SM_A 0
#define SM_B TILE_BYTES                       // two stages: + (t&1)*TILE_BYTES
#define SM_MISC (SM_B + 2 * TILE_BYTES)
#define SM_TOTAL (SM_MISC + 2 * BM * 4 + 64 + 64 * 4)

// ---------------- device scratch ----------------
__device__ uint8_t g_anchors[NB * D];        // e4m3
__device__ uint8_t g_rest[(size_t)NREST * D];
__device__ int   g_labels[NB];
__device__ float g_tot[NB];
__device__ float g_pos[NB];
__device__ unsigned g_done;

__device__ __forceinline__ uint32_t smem_u32(const void* p) {
    return (uint32_t)__cvta_generic_to_shared(p);
}
__device__ __forceinline__ void cp_async16(uint32_t dst, const void* src) {
    asm volatile("cp.async.cg.shared.global [%0], [%1], 16;" :: "r"(dst), "l"(src) : "memory");
}
__device__ __forceinline__ void cp_commit() {
    asm volatile("cp.async.commit_group;" ::: "memory");
}
template <int N>
__device__ __forceinline__ void cp_wait() {
    asm volatile("cp.async.wait_group %0;" :: "n"(N) : "memory");
}

// ---------------- kernel 1: normalize + init, write e4m3 ----------------
__global__ void normalize_kernel(const float* __restrict__ inp, const int* __restrict__ lab) {
    int gtid = blockIdx.x * 256 + threadIdx.x;
    if (gtid < NB) { g_tot[gtid] = 0.0f; g_pos[gtid] = 0.0f; g_labels[gtid] = lab[gtid]; }
    if (gtid == 0) g_done = 0u;

    int row  = blockIdx.x * 8 + (threadIdx.x >> 5);
    int lane = threadIdx.x & 31;
    const float4* p = reinterpret_cast<const float4*>(inp + (size_t)row * D) + lane * 2;
    float4 a = p[0];
    float4 b = p[1];
    float ss = a.x*a.x + a.y*a.y + a.z*a.z + a.w*a.w
             + b.x*b.x + b.y*b.y + b.z*b.z + b.w*b.w;
    #pragma unroll
    for (int o = 16; o > 0; o >>= 1) ss += __shfl_xor_sync(0xffffffffu, ss, o);
    float scale = 1.0f / fmaxf(sqrtf(ss), 1e-12f);

    int bidx = row >> 7;
    int l    = row & 127;
    uint8_t* dst = (l == 0)
        ? (g_anchors + (size_t)bidx * D)
        : (g_rest + (size_t)(bidx * (SEQ - 1) + (l - 1)) * D);

    __nv_fp8x2_storage_t q0 = __nv_cvt_float2_to_fp8x2(
        make_float2(a.x * scale, a.y * scale), __NV_SATFINITE, __NV_E4M3);
    __nv_fp8x2_storage_t q1 = __nv_cvt_float2_to_fp8x2(
        make_float2(a.z * scale, a.w * scale), __NV_SATFINITE, __NV_E4M3);
    __nv_fp8x2_storage_t q2 = __nv_cvt_float2_to_fp8x2(
        make_float2(b.x * scale, b.y * scale), __NV_SATFINITE, __NV_E4M3);
    __nv_fp8x2_storage_t q3 = __nv_cvt_float2_to_fp8x2(
        make_float2(b.z * scale, b.w * scale), __NV_SATFINITE, __NV_E4M3);
    uint2 u;
    u.x = (uint32_t)q0 | ((uint32_t)q1 << 16);
    u.y = (uint32_t)q2 | ((uint32_t)q3 << 16);
    *reinterpret_cast<uint2*>(dst + lane * 8) = u;
}

// ---------------- kernel 2: persistent FP8 GEMM, batch-aligned tiles ----------------
__global__ void __launch_bounds__(256, 2) score_kernel(float* __restrict__ out) {
    extern __shared__ __align__(16) char S[];

    float* sTot  = reinterpret_cast<float*>(S + SM_MISC);
    float* sPos  = sTot + BM;
    int*   sFlag = reinterpret_cast<int*>(sPos + BM);
    int*   sHist = sFlag + 16;

    int tid  = threadIdx.x;
    int lane = tid & 31;
    int warp = tid >> 5;
    int wm = (warp & 3) * 32;   // 4 warps along M
    int wn = (warp >> 2) * 64;  // 2 warps along N
    int bm = blockIdx.x * BM;
    int gy = blockIdx.y;
    int T  = (NTILES - gy + GRIDY - 1) / GRIDY;   // 7 or 6 tiles (batches)

    if (tid < BM) { sTot[tid] = 0.0f; sPos[tid] = 0.0f; }

    const uint8_t* gA = g_anchors + (size_t)bm * D;
    uint32_t smA = smem_u32(S + SM_A);
    uint32_t smB = smem_u32(S + SM_B);

    // zero the pad row (row 127) of both B stages once; never overwritten
    if (tid < 32) {
        int st = tid >> 4, c = tid & 15;
        *reinterpret_cast<uint4*>(S + SM_B + st * TILE_BYTES + 127 * SROW + c * 16) =
            make_uint4(0u, 0u, 0u, 0u);
    }

    // B tile load: 127 rows x 256B = 2032 16B-chunks
    #define ISSUE_B(t_, st_)                                                        \
        do {                                                                        \
            int _j = gy + (t_) * GRIDY;                                             \
            const uint8_t* _gB = g_rest + (size_t)_j * BROWS * D;                   \
            _Pragma("unroll")                                                       \
            for (int i = 0; i < 8; i++) {                                           \
                int idx = tid + i * 256;                                            \
                if (idx < BROWS * 16) {                                             \
                    int r = idx >> 4, c = idx & 15;                                 \
                    cp_async16(smB + (st_) * TILE_BYTES + r * SROW + c * 16,        \
                               _gB + (size_t)r * D + c * 16);                       \
                }                                                                   \
            }                                                                       \
            cp_commit();                                                            \
        } while (0)

    // prologue: A + B0 in group 0; B1 in group 1
    #pragma unroll
    for (int i = 0; i < 8; i++) {
        int idx = tid + i * 256;
        int r = idx >> 4, c = idx & 15;
        cp_async16(smA + r * SROW + c * 16, gA + (size_t)r * D + c * 16);
    }
    ISSUE_B(0, 0);        // commits group 0 (A + B0)
    ISSUE_B(1, 1);        // group 1

    // row labels fixed per thread for the whole kernel
    int qr = lane >> 2;
    int rlab[2][2];
    #pragma unroll
    for (int mf = 0; mf < 2; mf++)
        #pragma unroll
        for (int h = 0; h < 2; h++)
            rlab[mf][h] = g_labels[bm + wm + mf * 16 + h * 8 + qr];

    float rts[2][2] = {{0.f, 0.f}, {0.f, 0.f}};
    float rps[2][2] = {{0.f, 0.f}, {0.f, 0.f}};

    uint32_t afr[2][4], bfr[8][2];

    for (int t = 0; t < T; t++) {
        int j = gy + t * GRIDY;
        int jlab = g_labels[j];          // one label for the whole tile

        if (t + 1 < T) cp_wait<1>(); else cp_wait<0>();
        __syncthreads();

        uint32_t bBase = smB + (t & 1) * TILE_BYTES;

        float acc[2][8][4];
        #pragma unroll
        for (int mf = 0; mf < 2; mf++)
            #pragma unroll
            for (int nf = 0; nf < 8; nf++)
                #pragma unroll
                for (int r = 0; r < 4; r++) acc[mf][nf][r] = 0.0f;

        #pragma unroll
        for (int ks = 0; ks < 8; ks++) {
            #pragma unroll
            for (int mf = 0; mf < 2; mf++) {
                uint32_t addr = smA + (wm + mf * 16 + (lane & 15)) * SROW
                                    + ks * 32 + (lane >> 4) * 16;
                asm volatile("ldmatrix.sync.aligned.m8n8.x4.shared.b16 {%0,%1,%2,%3}, [%4];"
                             : "=r"(afr[mf][0]), "=r"(afr[mf][1]),
                               "=r"(afr[mf][2]), "=r"(afr[mf][3])
                             : "r"(addr));
            }
            #pragma unroll
            for (int np = 0; np < 4; np++) {
                uint32_t addr = bBase + (wn + np * 16 + (lane >> 4) * 8 + (lane & 7)) * SROW
                                      + ks * 32 + ((lane >> 3) & 1) * 16;
                asm volatile("ldmatrix.sync.aligned.m8n8.x4.shared.b16 {%0,%1,%2,%3}, [%4];"
                             : "=r"(bfr[2 * np][0]), "=r"(bfr[2 * np][1]),
                               "=r"(bfr[2 * np + 1][0]), "=r"(bfr[2 * np + 1][1])
                             : "r"(addr));
            }
            #pragma unroll
            for (int mf = 0; mf < 2; mf++)
                #pragma unroll
                for (int nf = 0; nf < 8; nf++)
                    asm volatile(
                        "mma.sync.aligned.m16n8k32.row.col.f32.e4m3.e4m3.f32 "
                        "{%0,%1,%2,%3}, {%4,%5,%6,%7}, {%8,%9}, {%0,%1,%2,%3};"
                        : "+f"(acc[mf][nf][0]), "+f"(acc[mf][nf][1]),
                          "+f"(acc[mf][nf][2]), "+f"(acc[mf][nf][3])
                        : "r"(afr[mf][0]), "r"(afr[mf][1]), "r"(afr[mf][2]), "r"(afr[mf][3]),
                          "r"(bfr[nf][0]), "r"(bfr[nf][1]));
        }

        // epilogue: exp + row sum; single label compare per (row,tile)
        #pragma unroll
        for (int mf = 0; mf < 2; mf++) {
            #pragma unroll
            for (int h = 0; h < 2; h++) {
                float ts = 0.0f;
                #pragma unroll
                for (int nf = 0; nf < 8; nf++) {
                    ts += __expf(acc[mf][nf][h * 2 + 0]);
                    ts += __expf(acc[mf][nf][h * 2 + 1]);
                }
                ts += __shfl_xor_sync(0xffffffffu, ts, 1);
                ts += __shfl_xor_sync(0xffffffffu, ts, 2);
                if ((lane & 3) == 0) {
                    rts[mf][h] += ts;
                    rps[mf][h] += (jlab == rlab[mf][h]) ? ts : 0.0f;
                }
            }
        }

        // stage (t&1) fully consumed -> refill
        __syncthreads();
        if (t + 2 < T) ISSUE_B(t + 2, t & 1);
    }

    // drain per-thread accumulators -> smem -> global
    if ((lane & 3) == 0) {
        #pragma unroll
        for (int mf = 0; mf < 2; mf++)
            #pragma unroll
            for (int h = 0; h < 2; h++) {
                int lrow = wm + mf * 16 + h * 8 + qr;
                atomicAdd(&sTot[lrow], rts[mf][h]);
                atomicAdd(&sPos[lrow], rps[mf][h]);
            }
    }
    __syncthreads();
    if (tid < BM) {
        atomicAdd(&g_tot[bm + tid], sTot[tid]);
        atomicAdd(&g_pos[bm + tid], sPos[tid]);
    }

    // ---- fused finalize: last CTA computes the loss ----
    __threadfence();
    __syncthreads();
    if (tid == 0) {
        unsigned v = atomicAdd(&g_done, 1u);
        sFlag[0] = (v == TOTAL_BLOCKS - 1) ? 1 : 0;
    }
    __syncthreads();
    if (sFlag[0]) {
        __threadfence();
        // histogram of labels (pad-column correction for pos)
        if (tid < 64) sHist[tid] = 0;
        __syncthreads();
        int l0 = g_labels[tid], l1 = g_labels[tid + 256];
        atomicAdd(&sHist[l0], 1);
        atomicAdd(&sHist[l1], 1);
        __syncthreads();
        // every tile adds exp(0)=1 to tot; same-label tiles add 1 to pos
        float v = (logf(g_tot[tid]       - 512.0f) - logf(g_pos[tid]       - (float)sHist[l0]))
                + (logf(g_tot[tid + 256] - 512.0f) - logf(g_pos[tid + 256] - (float)sHist[l1]));
        #pragma unroll
        for (int o = 16; o > 0; o >>= 1) v += __shfl_xor_sync(0xffffffffu, v, o);
        float* red = sTot;   // reuse
        if (lane == 0) red[warp] = v;
        __syncthreads();
        if (tid == 0) {
            float s = 0.0f;
            #pragma unroll
            for (int w = 0; w < 8; w++) s += red[w];
            out[0] = s * (1.0f / 512.0f);
        }
    }
}

// ---------------- launch ----------------
extern "C" void kernel_launch(void* const* d_in, const int* in_sizes, int n_in,
                              void* d_out, int out_size) {
    const float* inp = (const float*)d_in[0];
    const int*   lab = (const int*)d_in[1];
    float*       out = (float*)d_out;

    cudaFuncSetAttribute(score_kernel, cudaFuncAttributeMaxDynamicSharedMemorySize, SM_TOTAL);

    normalize_kernel<<<(NB * SEQ) / 8, 256>>>(inp, lab);
    score_kernel<<<dim3(GRIDX, GRIDY), 256, SM_TOTAL>>>(out);
}